// round 3
// baseline (speedup 1.0000x reference)
#include <cuda_runtime.h>
#include <math.h>

#define BB 32
#define CC 256
#define NN 1024
#define O3 768
#define NGROUP 32
#define GN_EPS 1e-5f

// ------------------------- scratch (device globals; no allocs) ---------------
__device__ float g_qkv[BB * O3 * NN];       // 100.7 MB
__device__ float g_attn[BB * NN * NN];      // 134.2 MB (scores -> softmax in place)
__device__ float g_xattn[BB * CC * NN];     //  33.5 MB
__device__ float g_pooled[BB * CC];
__device__ float g_gate[BB * CC];
__device__ float g_gnsc[BB * CC];           // per (b,c) GN scale  = gamma*rstd
__device__ float g_gnof[BB * CC];           // per (b,c) GN offset = beta - mean*scale
__device__ float g_wqkvT[CC * O3];
__device__ float g_wprojT[CC * CC];

// buffer selector so host code never touches device symbols
__device__ __forceinline__ float* buf(int s) {
    switch (s) {
        case 1: return g_qkv;
        case 2: return g_attn;
        case 3: return g_xattn;
        case 4: return g_wqkvT;
        case 5: return g_wprojT;
        default: return nullptr;
    }
}

// ------------------------- small helpers -------------------------------------
__device__ __forceinline__ float warpSum(float v) {
    #pragma unroll
    for (int o = 16; o; o >>= 1) v += __shfl_xor_sync(0xFFFFFFFFu, v, o);
    return v;
}
__device__ __forceinline__ float warpMax(float v) {
    #pragma unroll
    for (int o = 16; o; o >>= 1) v = fmaxf(v, __shfl_xor_sync(0xFFFFFFFFu, v, o));
    return v;
}

// ------------------------- weight transpose (tiny) ---------------------------
__global__ void transpose_k(const float* __restrict__ in, int outSel,
                            int R, int Cc) {
    float* out = buf(outSel);
    int i = blockIdx.x * 256 + threadIdx.x;
    if (i < R * Cc) {
        int r = i / Cc, c = i % Cc;
        out[c * R + r] = in[i];
    }
}

// ------------------------- GN stats + pooled mean (one pass over x) ----------
// block = (group g, batch b); 8 channels * 1024 spatial, thread t reads
// element t*4 + it*1024 where it == channel-within-group.
__global__ void gn_stats_k(const float* __restrict__ x,
                           const float* __restrict__ gamma,
                           const float* __restrict__ beta) {
    int g = blockIdx.x, b = blockIdx.y;
    long base = ((long)b * CC + g * 8) * NN;
    const float* p = x + base;
    int t = threadIdx.x;
    int lane = t & 31, w = t >> 5;

    float cs[8];     // per-channel partial sums
    float ss = 0.f;  // group partial sum of squares
    #pragma unroll
    for (int it = 0; it < 8; it++) {
        float4 v = *(const float4*)&p[t * 4 + it * 1024];
        cs[it] = v.x + v.y + v.z + v.w;
        ss += v.x * v.x + v.y * v.y + v.z * v.z + v.w * v.w;
    }
    #pragma unroll
    for (int it = 0; it < 8; it++) cs[it] = warpSum(cs[it]);
    ss = warpSum(ss);

    __shared__ float rcs[8][8];   // [warp][channel]
    __shared__ float rss[8];
    __shared__ float smean, srstd;
    if (lane == 0) {
        #pragma unroll
        for (int it = 0; it < 8; it++) rcs[w][it] = cs[it];
        rss[w] = ss;
    }
    __syncthreads();
    __shared__ float chsum[8];
    if (t < 8) {                 // t = channel-within-group
        float a = 0.f;
        #pragma unroll
        for (int i = 0; i < 8; i++) a += rcs[i][t];
        chsum[t] = a;
        g_pooled[b * CC + g * 8 + t] = a * (1.0f / 1024.0f);
    }
    __syncthreads();
    if (t == 0) {
        float a = 0.f, c2 = 0.f;
        #pragma unroll
        for (int i = 0; i < 8; i++) { a += chsum[i]; c2 += rss[i]; }
        float mean = a * (1.0f / 8192.0f);
        float var = c2 * (1.0f / 8192.0f) - mean * mean;
        smean = mean;
        srstd = rsqrtf(var + GN_EPS);
    }
    __syncthreads();
    if (t < 8) {
        int c = g * 8 + t;
        float sc = gamma[c] * srstd;
        g_gnsc[b * CC + c] = sc;
        g_gnof[b * CC + c] = beta[c] - smean * sc;
    }
}

// ------------------------- SE gate -------------------------------------------
__global__ void se_k(const float* __restrict__ w1, const float* __restrict__ b1,
                     const float* __restrict__ w2, const float* __restrict__ b2) {
    int b = blockIdx.x;
    int t = threadIdx.x;
    __shared__ float pool[CC];
    __shared__ float h1[64];
    pool[t] = g_pooled[b * CC + t];
    __syncthreads();
    if (t < 64) {
        float s = b1[t];
        const float* wr = w1 + t * CC;
        #pragma unroll 8
        for (int c = 0; c < CC; c++) s += wr[c] * pool[c];
        h1[t] = fmaxf(s, 0.0f);
    }
    __syncthreads();
    float s = b2[t];
    const float* wr = w2 + t * 64;
    #pragma unroll
    for (int j = 0; j < 64; j++) s += wr[j] * h1[j];
    g_gate[b * CC + t] = 1.0f / (1.0f + expf(-s));
}

// ------------------------- TN GEMM: out[m,n] = sum_k A[k,m] * B[k,n] ---------
// A: [K,M] k-major (lda=M); B: [K,N] k-major (ldb=N)
// NORM: apply per-(b,k) affine (g_gnsc/g_gnof) to B elements while loading
// EPI 0: out = acc + bias[m]
// EPI 1: out = acc * alpha
// EPI 2: out = resid + gate[b*M+m] * (acc + bias[m])
template <int EPI, bool NORM>
__global__ __launch_bounds__(256) void gemm_tn(
    int aSel, const float* __restrict__ aExt, long offA, long strideA,
    int bSel, const float* __restrict__ bExt, long offB, long strideB,
    int cSel, float* __restrict__ cExt, long strideC,
    int M, int N, int K, float alpha,
    const float* __restrict__ bias,
    const float* __restrict__ resid, long strideR) {
    __shared__ float As[16][128];
    __shared__ float Bs[16][128];
    int b = blockIdx.z;
    const float* Abase = (aSel >= 0) ? buf(aSel) : aExt;
    const float* Bbase = (bSel >= 0) ? buf(bSel) : bExt;
    float* Cbase = (cSel >= 0) ? buf(cSel) : cExt;
    const float* Ap = Abase + offA + (long)b * strideA;
    const float* Bp = Bbase + offB + (long)b * strideB;
    float* Cp = Cbase + (long)b * strideC;
    int m0 = blockIdx.y * 128;
    int n0 = blockIdx.x * 128;
    int t = threadIdx.x;
    int tx = t & 15, ty = t >> 4;

    float acc[8][8];
    #pragma unroll
    for (int i = 0; i < 8; i++)
        #pragma unroll
        for (int j = 0; j < 8; j++) acc[i][j] = 0.f;

    for (int k0 = 0; k0 < K; k0 += 16) {
        #pragma unroll
        for (int p = 0; p < 2; ++p) {
            int idx = t + p * 256;           // 0..511 float4 slots
            int kk = idx >> 5;               // 32 float4 per 128-wide row
            int m4 = (idx & 31) << 2;
            *(float4*)&As[kk][m4] = *(const float4*)&Ap[(long)(k0 + kk) * M + m0 + m4];
            float4 bv = *(const float4*)&Bp[(long)(k0 + kk) * N + n0 + m4];
            if (NORM) {
                float sck = g_gnsc[b * CC + k0 + kk];
                float ofk = g_gnof[b * CC + k0 + kk];
                bv.x = bv.x * sck + ofk; bv.y = bv.y * sck + ofk;
                bv.z = bv.z * sck + ofk; bv.w = bv.w * sck + ofk;
            }
            *(float4*)&Bs[kk][m4] = bv;
        }
        __syncthreads();
        #pragma unroll
        for (int kk = 0; kk < 16; ++kk) {
            float af[8], bf[8];
            *(float4*)&af[0] = *(float4*)&As[kk][ty * 8];
            *(float4*)&af[4] = *(float4*)&As[kk][ty * 8 + 4];
            *(float4*)&bf[0] = *(float4*)&Bs[kk][tx * 8];
            *(float4*)&bf[4] = *(float4*)&Bs[kk][tx * 8 + 4];
            #pragma unroll
            for (int i = 0; i < 8; i++)
                #pragma unroll
                for (int j = 0; j < 8; j++) acc[i][j] += af[i] * bf[j];
        }
        __syncthreads();
    }

    #pragma unroll
    for (int i = 0; i < 8; i++) {
        int m = m0 + ty * 8 + i;
        float bi = (EPI == 1) ? 0.f : bias[m];
        float gv = (EPI == 2) ? g_gate[b * M + m] : 0.f;
        #pragma unroll
        for (int j4 = 0; j4 < 2; j4++) {
            int n = n0 + tx * 8 + j4 * 4;
            float* pa = &acc[i][j4 * 4];
            float4 r;
            if (EPI == 0) {
                r.x = pa[0] + bi; r.y = pa[1] + bi; r.z = pa[2] + bi; r.w = pa[3] + bi;
            } else if (EPI == 1) {
                r.x = pa[0] * alpha; r.y = pa[1] * alpha;
                r.z = pa[2] * alpha; r.w = pa[3] * alpha;
            } else {
                float4 rv = *(const float4*)&resid[(long)b * strideR + (long)m * N + n];
                r.x = rv.x + gv * (pa[0] + bi);
                r.y = rv.y + gv * (pa[1] + bi);
                r.z = rv.z + gv * (pa[2] + bi);
                r.w = rv.w + gv * (pa[3] + bi);
            }
            *(float4*)&Cp[(long)m * N + n] = r;
        }
    }
}

// ------------------------- softmax rows (32768 x 1024, in place) -------------
__global__ void softmax_k() {
    int row = blockIdx.x;                  // b*NN + i
    float* p = g_attn + (long)row * NN;
    int t = threadIdx.x;
    float4 v = *(float4*)&p[t * 4];
    float m = fmaxf(fmaxf(v.x, v.y), fmaxf(v.z, v.w));
    m = warpMax(m);
    __shared__ float rs[8];
    __shared__ float bc;
    int lane = t & 31, w = t >> 5;
    if (lane == 0) rs[w] = m;
    __syncthreads();
    if (t == 0) {
        float mm = rs[0];
        #pragma unroll
        for (int i = 1; i < 8; i++) mm = fmaxf(mm, rs[i]);
        bc = mm;
    }
    __syncthreads();
    m = bc;
    v.x = expf(v.x - m); v.y = expf(v.y - m);
    v.z = expf(v.z - m); v.w = expf(v.w - m);
    float s = v.x + v.y + v.z + v.w;
    s = warpSum(s);
    if (lane == 0) rs[w] = s;
    __syncthreads();
    if (t == 0) {
        float ss = 0.f;
        #pragma unroll
        for (int i = 0; i < 8; i++) ss += rs[i];
        bc = 1.0f / ss;
    }
    __syncthreads();
    float inv = bc;
    v.x *= inv; v.y *= inv; v.z *= inv; v.w *= inv;
    *(float4*)&p[t * 4] = v;
}

// ------------------------- NT GEMM: x_attn[c,i] = sum_j v[c,j]*attn[i,j] -----
__global__ __launch_bounds__(256) void gemm_nt_xattn() {
    int b = blockIdx.z;
    const float* vmat = g_qkv + ((long)b * O3 + 2 * CC) * NN;  // v rows
    const float* at = g_attn + (long)b * NN * NN;
    float* Cp = g_xattn + (long)b * CC * NN;
    int c0 = blockIdx.y * 128;
    int i0 = blockIdx.x * 128;
    int t = threadIdx.x;
    int tx = t & 15, ty = t >> 4;
    __shared__ float As[16][136];
    __shared__ float Bs[16][136];

    float acc[8][8];
    #pragma unroll
    for (int i = 0; i < 8; i++)
        #pragma unroll
        for (int j = 0; j < 8; j++) acc[i][j] = 0.f;

    int ct = t >> 1, jb = (t & 1) * 8;
    for (int j0 = 0; j0 < NN; j0 += 16) {
        float4 a0 = *(const float4*)&vmat[(long)(c0 + ct) * NN + j0 + jb];
        float4 a1 = *(const float4*)&vmat[(long)(c0 + ct) * NN + j0 + jb + 4];
        float4 b0 = *(const float4*)&at[(long)(i0 + ct) * NN + j0 + jb];
        float4 b1 = *(const float4*)&at[(long)(i0 + ct) * NN + j0 + jb + 4];
        As[jb + 0][ct] = a0.x; As[jb + 1][ct] = a0.y;
        As[jb + 2][ct] = a0.z; As[jb + 3][ct] = a0.w;
        As[jb + 4][ct] = a1.x; As[jb + 5][ct] = a1.y;
        As[jb + 6][ct] = a1.z; As[jb + 7][ct] = a1.w;
        Bs[jb + 0][ct] = b0.x; Bs[jb + 1][ct] = b0.y;
        Bs[jb + 2][ct] = b0.z; Bs[jb + 3][ct] = b0.w;
        Bs[jb + 4][ct] = b1.x; Bs[jb + 5][ct] = b1.y;
        Bs[jb + 6][ct] = b1.z; Bs[jb + 7][ct] = b1.w;
        __syncthreads();
        #pragma unroll
        for (int kk = 0; kk < 16; ++kk) {
            float af[8], bf[8];
            *(float4*)&af[0] = *(float4*)&As[kk][ty * 8];
            *(float4*)&af[4] = *(float4*)&As[kk][ty * 8 + 4];
            *(float4*)&bf[0] = *(float4*)&Bs[kk][tx * 8];
            *(float4*)&bf[4] = *(float4*)&Bs[kk][tx * 8 + 4];
            #pragma unroll
            for (int i = 0; i < 8; i++)
                #pragma unroll
                for (int j = 0; j < 8; j++) acc[i][j] += af[i] * bf[j];
        }
        __syncthreads();
    }

    #pragma unroll
    for (int i = 0; i < 8; i++) {
        int c = c0 + ty * 8 + i;
        #pragma unroll
        for (int j4 = 0; j4 < 2; j4++) {
            float* pa = &acc[i][j4 * 4];
            float4 r = make_float4(pa[0], pa[1], pa[2], pa[3]);
            *(float4*)&Cp[(long)c * NN + i0 + tx * 8 + j4 * 4] = r;
        }
    }
}

// ------------------------- launch --------------------------------------------
extern "C" void kernel_launch(void* const* d_in, const int* in_sizes, int n_in,
                              void* d_out, int out_size) {
    const float* x        = (const float*)d_in[0];
    const float* gn_gamma = (const float*)d_in[1];
    const float* gn_beta  = (const float*)d_in[2];
    const float* w_qkv    = (const float*)d_in[3];
    const float* b_qkv    = (const float*)d_in[4];
    const float* w_proj   = (const float*)d_in[5];
    const float* b_proj   = (const float*)d_in[6];
    const float* w_se1    = (const float*)d_in[7];
    const float* b_se1    = (const float*)d_in[8];
    const float* w_se2    = (const float*)d_in[9];
    const float* b_se2    = (const float*)d_in[10];
    float* out = (float*)d_out;

    // weight transposes (k-major for TN GEMMs)
    transpose_k<<<(O3 * CC + 255) / 256, 256>>>(w_qkv, 4, O3, CC);
    transpose_k<<<(CC * CC + 255) / 256, 256>>>(w_proj, 5, CC, CC);

    // GN stats (sc/of per b,c) + pooled means, one pass over x
    gn_stats_k<<<dim3(NGROUP, BB), 256>>>(x, gn_gamma, gn_beta);

    // SE gate from pooled
    se_k<<<BB, 256>>>(w_se1, b_se1, w_se2, b_se2);

    // QKV: [768,1024] = wqkvT^T @ GN(x) per batch, + bias  (GN folded into B load)
    gemm_tn<0, true><<<dim3(NN / 128, O3 / 128, BB), 256>>>(
        4, nullptr, 0L, 0L,                  // A = g_wqkvT, shared
        -1, x, 0L, (long)CC * NN,            // B = x (normalized on the fly)
        1, nullptr, (long)O3 * NN,           // C = g_qkv
        O3, NN, CC, 1.0f, b_qkv, nullptr, 0L);

    // scores[i,j] = (1/16) * sum_c q[c,i] k[c,j]  -> g_attn
    gemm_tn<1, false><<<dim3(NN / 128, NN / 128, BB), 256>>>(
        1, nullptr, 0L, (long)O3 * NN,                 // A = q rows of g_qkv
        1, nullptr, (long)CC * NN, (long)O3 * NN,      // B = k rows of g_qkv
        2, nullptr, (long)NN * NN,                     // C = g_attn
        NN, NN, CC, 0.0625f, nullptr, nullptr, 0L);

    // softmax over last dim, in place
    softmax_k<<<BB * NN, 256>>>();

    // x_attn = v @ attn^T -> g_xattn
    gemm_nt_xattn<<<dim3(NN / 128, CC / 128, BB), 256>>>();

    // proj + SE-gated residual -> out
    gemm_tn<2, false><<<dim3(NN / 128, CC / 128, BB), 256>>>(
        5, nullptr, 0L, 0L,                  // A = g_wprojT
        3, nullptr, 0L, (long)CC * NN,       // B = g_xattn
        -1, out, (long)CC * NN,              // C = harness output
        CC, NN, CC, 1.0f, b_proj, x, (long)CC * NN);
}

// round 9
// speedup vs baseline: 4.0222x; 4.0222x over previous
#include <cuda_runtime.h>
#include <cuda_bf16.h>
#include <math.h>
#include <stdint.h>

#define BB 32
#define CC 256
#define NN 1024
#define O3 768
#define NGROUP 32
#define GN_EPS 1e-5f

// ------------------------- scratch (device globals; no allocs) ---------------
__device__ __nv_bfloat16 g_xnT[BB * NN * CC];         // 16.8 MB  [b, n, c]
__device__ __nv_bfloat16 g_qkvT[BB * NN * O3];        // 50.3 MB  [b, n, o]
__device__ float         g_attn[(long)BB * NN * NN];  // 134 MB   [b, i, j] fp32 scores
__device__ __nv_bfloat16 g_attnb[(long)BB * NN * NN]; // 67 MB    [b, i, j] bf16 softmaxed
__device__ __nv_bfloat16 g_vK[BB * CC * NN];          // 16.8 MB  [b, c, j]
__device__ __nv_bfloat16 g_xattnT[BB * NN * CC];      // 16.8 MB  [b, i, c]
__device__ __nv_bfloat16 g_wqkv_b[O3 * CC];
__device__ __nv_bfloat16 g_wproj_b[CC * CC];
__device__ float g_pooled[BB * CC];
__device__ float g_gate[BB * CC];
__device__ float g_gnsc[BB * CC];
__device__ float g_gnof[BB * CC];

__device__ __forceinline__ void* buf(int s) {
    switch (s) {
        case 0: return (void*)g_xnT;
        case 1: return (void*)g_qkvT;
        case 2: return (void*)g_attn;
        case 3: return (void*)g_attnb;
        case 4: return (void*)g_vK;
        case 5: return (void*)g_xattnT;
        case 6: return (void*)g_wqkv_b;
        case 7: return (void*)g_wproj_b;
        default: return nullptr;
    }
}

// ------------------------- PTX macros (no pointer/reference indirection) -----
__device__ __forceinline__ uint32_t smem_u32(const void* p) {
    return (uint32_t)__cvta_generic_to_shared(p);
}
#define CP16(dst, src) \
    asm volatile("cp.async.cg.shared.global [%0], [%1], 16;" :: "r"(dst), "l"(src))
#define CP_COMMIT() asm volatile("cp.async.commit_group;")
#define CP_WAIT(N)  asm volatile("cp.async.wait_group %0;" :: "n"(N))

#define LDM4(f0, f1, f2, f3, addr) \
    asm volatile("ldmatrix.sync.aligned.m8n8.x4.shared.b16 {%0,%1,%2,%3}, [%4];" \
                 : "=r"(f0), "=r"(f1), "=r"(f2), "=r"(f3) : "r"(addr))

#define MMA16(d0, d1, d2, d3, a0, a1, a2, a3, b0, b1) \
    asm volatile( \
        "mma.sync.aligned.m16n8k16.row.col.f32.bf16.bf16.f32 " \
        "{%0,%1,%2,%3}, {%4,%5,%6,%7}, {%8,%9}, {%0,%1,%2,%3};" \
        : "+f"(d0), "+f"(d1), "+f"(d2), "+f"(d3) \
        : "r"(a0), "r"(a1), "r"(a2), "r"(a3), "r"(b0), "r"(b1))

struct U4 { uint32_t a, b, c, d; };
struct F4 { float a, b, c, d; };

__device__ __forceinline__ uint32_t swz_addr(int r, int seg) {
    return (uint32_t)(r * 64 + ((seg ^ ((r >> 1) & 3)) << 4));
}

__device__ __forceinline__ float warpSum(float v) {
    #pragma unroll
    for (int o = 16; o; o >>= 1) v += __shfl_xor_sync(0xFFFFFFFFu, v, o);
    return v;
}
__device__ __forceinline__ float warpMax(float v) {
    #pragma unroll
    for (int o = 16; o; o >>= 1) v = fmaxf(v, __shfl_xor_sync(0xFFFFFFFFu, v, o));
    return v;
}

// ------------------------- fp32 -> bf16 weight convert -----------------------
__global__ void convw_k(const float* __restrict__ in, int outSel, int n) {
    __nv_bfloat16* out = (__nv_bfloat16*)buf(outSel);
    int i = blockIdx.x * 256 + threadIdx.x;
    if (i < n) out[i] = __float2bfloat16(in[i]);
}

// ------------------------- GN stats + pooled mean ----------------------------
__global__ void gn_stats_k(const float* __restrict__ x,
                           const float* __restrict__ gamma,
                           const float* __restrict__ beta) {
    int g = blockIdx.x, b = blockIdx.y;
    long base = ((long)b * CC + g * 8) * NN;
    const float* p = x + base;
    int t = threadIdx.x;
    int lane = t & 31, w = t >> 5;

    float cs[8];
    float ss = 0.f;
    #pragma unroll
    for (int it = 0; it < 8; it++) {
        float4 v = *(const float4*)&p[t * 4 + it * 1024];
        cs[it] = v.x + v.y + v.z + v.w;
        ss += v.x * v.x + v.y * v.y + v.z * v.z + v.w * v.w;
    }
    #pragma unroll
    for (int it = 0; it < 8; it++) cs[it] = warpSum(cs[it]);
    ss = warpSum(ss);

    __shared__ float rcs[8][8];
    __shared__ float rss[8];
    __shared__ float smean, srstd;
    __shared__ float chsum[8];
    if (lane == 0) {
        #pragma unroll
        for (int it = 0; it < 8; it++) rcs[w][it] = cs[it];
        rss[w] = ss;
    }
    __syncthreads();
    if (t < 8) {
        float a = 0.f;
        #pragma unroll
        for (int i = 0; i < 8; i++) a += rcs[i][t];
        chsum[t] = a;
        g_pooled[b * CC + g * 8 + t] = a * (1.0f / 1024.0f);
    }
    __syncthreads();
    if (t == 0) {
        float a = 0.f, c2 = 0.f;
        #pragma unroll
        for (int i = 0; i < 8; i++) { a += chsum[i]; c2 += rss[i]; }
        float mean = a * (1.0f / 8192.0f);
        float var = c2 * (1.0f / 8192.0f) - mean * mean;
        smean = mean;
        srstd = rsqrtf(var + GN_EPS);
    }
    __syncthreads();
    if (t < 8) {
        int c = g * 8 + t;
        float sc = gamma[c] * srstd;
        g_gnsc[b * CC + c] = sc;
        g_gnof[b * CC + c] = beta[c] - smean * sc;
    }
}

// ------------------------- SE gate -------------------------------------------
__global__ void se_k(const float* __restrict__ w1, const float* __restrict__ b1,
                     const float* __restrict__ w2, const float* __restrict__ b2) {
    int b = blockIdx.x;
    int t = threadIdx.x;
    __shared__ float pool[CC];
    __shared__ float h1[64];
    pool[t] = g_pooled[b * CC + t];
    __syncthreads();
    if (t < 64) {
        float s = b1[t];
        const float* wr = w1 + t * CC;
        #pragma unroll 8
        for (int c = 0; c < CC; c++) s += wr[c] * pool[c];
        h1[t] = fmaxf(s, 0.0f);
    }
    __syncthreads();
    float s = b2[t];
    const float* wr = w2 + t * 64;
    #pragma unroll
    for (int j = 0; j < 64; j++) s += wr[j] * h1[j];
    g_gate[b * CC + t] = 1.0f / (1.0f + expf(-s));
}

// ------------------------- xnT: GN(x) transposed to [b,n,c] bf16 -------------
__global__ void xnT_k(const float* __restrict__ x) {
    __shared__ float tile[32][33];
    int b = blockIdx.z;
    int cblk = blockIdx.y * 32, nblk = blockIdx.x * 32;
    int tx = threadIdx.x, ty = threadIdx.y;   // (32, 8)
    #pragma unroll
    for (int i = 0; i < 4; i++) {
        int c = cblk + ty + i * 8;
        float sc = g_gnsc[b * CC + c];
        float of = g_gnof[b * CC + c];
        tile[ty + i * 8][tx] = x[((long)b * CC + c) * NN + nblk + tx] * sc + of;
    }
    __syncthreads();
    #pragma unroll
    for (int i = 0; i < 4; i++) {
        int n = nblk + ty + i * 8;
        g_xnT[((long)b * NN + n) * CC + cblk + tx] = __float2bfloat16(tile[tx][ty + i * 8]);
    }
}

// ------------------------- vT: qkvT[:,512:768] -> vK [b,c,j] -----------------
__global__ void vT_k() {
    __shared__ __nv_bfloat16 tile[32][33];
    int b = blockIdx.z;
    int cblk = blockIdx.y * 32, jblk = blockIdx.x * 32;
    int tx = threadIdx.x, ty = threadIdx.y;   // (32, 8)
    #pragma unroll
    for (int i = 0; i < 4; i++) {
        int j = jblk + ty + i * 8;
        tile[ty + i * 8][tx] = g_qkvT[((long)b * NN + j) * O3 + 512 + cblk + tx];
    }
    __syncthreads();
    #pragma unroll
    for (int i = 0; i < 4; i++) {
        int c = cblk + ty + i * 8;
        g_vK[((long)b * CC + c) * NN + jblk + tx] = tile[tx][ty + i * 8];
    }
}

// ------------------------- softmax rows: fp32 in, bf16 out -------------------
__global__ void softmax_k() {
    long row = blockIdx.x;
    float* p = g_attn + row * NN;
    __nv_bfloat16* q = g_attnb + row * NN;
    int t = threadIdx.x;
    float4 v = *(float4*)&p[t * 4];
    float m = fmaxf(fmaxf(v.x, v.y), fmaxf(v.z, v.w));
    m = warpMax(m);
    __shared__ float rs[8];
    __shared__ float bc;
    int lane = t & 31, w = t >> 5;
    if (lane == 0) rs[w] = m;
    __syncthreads();
    if (t == 0) {
        float mm = rs[0];
        #pragma unroll
        for (int i = 1; i < 8; i++) mm = fmaxf(mm, rs[i]);
        bc = mm;
    }
    __syncthreads();
    m = bc;
    v.x = expf(v.x - m); v.y = expf(v.y - m);
    v.z = expf(v.z - m); v.w = expf(v.w - m);
    float s = v.x + v.y + v.z + v.w;
    s = warpSum(s);
    if (lane == 0) rs[w] = s;
    __syncthreads();
    if (t == 0) {
        float ss = 0.f;
        #pragma unroll
        for (int i = 0; i < 8; i++) ss += rs[i];
        bc = 1.0f / ss;
    }
    __syncthreads();
    float inv = bc;
    __nv_bfloat162 lo = __floats2bfloat162_rn(v.x * inv, v.y * inv);
    __nv_bfloat162 hi = __floats2bfloat162_rn(v.z * inv, v.w * inv);
    uint2 pk;
    pk.x = *(uint32_t*)&lo;
    pk.y = *(uint32_t*)&hi;
    *(uint2*)&q[t * 4] = pk;
}

// ------------------------- HMMA GEMM: D[M,N] = A[M,K] @ B[N,K]^T -------------
// A, B bf16 K-major. Block tile 128x128, BK=32, 2-stage cp.async double buffer.
// 8 warps, each 64x32 (4x4 m16n8k16 tiles). Named structs only (register-safe).
// EPI 3 reads g_gate DIRECTLY (device symbol must not be passed from host!).

#define MMA_ALL() do { \
    MMA16(c00.a,c00.b,c00.c,c00.d, af0.a,af0.b,af0.c,af0.d, bf0.a,bf0.c); \
    MMA16(c01.a,c01.b,c01.c,c01.d, af0.a,af0.b,af0.c,af0.d, bf0.b,bf0.d); \
    MMA16(c02.a,c02.b,c02.c,c02.d, af0.a,af0.b,af0.c,af0.d, bf1.a,bf1.c); \
    MMA16(c03.a,c03.b,c03.c,c03.d, af0.a,af0.b,af0.c,af0.d, bf1.b,bf1.d); \
    MMA16(c10.a,c10.b,c10.c,c10.d, af1.a,af1.b,af1.c,af1.d, bf0.a,bf0.c); \
    MMA16(c11.a,c11.b,c11.c,c11.d, af1.a,af1.b,af1.c,af1.d, bf0.b,bf0.d); \
    MMA16(c12.a,c12.b,c12.c,c12.d, af1.a,af1.b,af1.c,af1.d, bf1.a,bf1.c); \
    MMA16(c13.a,c13.b,c13.c,c13.d, af1.a,af1.b,af1.c,af1.d, bf1.b,bf1.d); \
    MMA16(c20.a,c20.b,c20.c,c20.d, af2.a,af2.b,af2.c,af2.d, bf0.a,bf0.c); \
    MMA16(c21.a,c21.b,c21.c,c21.d, af2.a,af2.b,af2.c,af2.d, bf0.b,bf0.d); \
    MMA16(c22.a,c22.b,c22.c,c22.d, af2.a,af2.b,af2.c,af2.d, bf1.a,bf1.c); \
    MMA16(c23.a,c23.b,c23.c,c23.d, af2.a,af2.b,af2.c,af2.d, bf1.b,bf1.d); \
    MMA16(c30.a,c30.b,c30.c,c30.d, af3.a,af3.b,af3.c,af3.d, bf0.a,bf0.c); \
    MMA16(c31.a,c31.b,c31.c,c31.d, af3.a,af3.b,af3.c,af3.d, bf0.b,bf0.d); \
    MMA16(c32.a,c32.b,c32.c,c32.d, af3.a,af3.b,af3.c,af3.d, bf1.a,bf1.c); \
    MMA16(c33.a,c33.b,c33.c,c33.d, af3.a,af3.b,af3.c,af3.d, bf1.b,bf1.d); \
} while (0)

#define LOAD_MMA(KOFF) do { \
    U4 af0, af1, af2, af3, bf0, bf1; \
    LDM4(af0.a,af0.b,af0.c,af0.d, aBase + (ar0 ^ (KOFF))); \
    LDM4(af1.a,af1.b,af1.c,af1.d, aBase + (ar1 ^ (KOFF))); \
    LDM4(af2.a,af2.b,af2.c,af2.d, aBase + (ar2 ^ (KOFF))); \
    LDM4(af3.a,af3.b,af3.c,af3.d, aBase + (ar3 ^ (KOFF))); \
    LDM4(bf0.a,bf0.b,bf0.c,bf0.d, bBase + (br0 ^ (KOFF))); \
    LDM4(bf1.a,bf1.b,bf1.c,bf1.d, bBase + (br1 ^ (KOFF))); \
    MMA_ALL(); \
} while (0)

template <int EPI>
__global__ __launch_bounds__(256) void gemm_mma(
    int aSel, const void* aExt, long aOff, long aStride, int ldA,
    int bSel, const void* bExt, long bOff, long bStride, int ldB,
    int cSel, void* cExt, long cStride, int ldC,
    int K, float alpha,
    const float* __restrict__ bias,
    const float* __restrict__ resid, long strideR) {
    __shared__ alignas(1024) uint8_t sA[2][128 * 64];
    __shared__ alignas(1024) uint8_t sB[2][128 * 64];

    int b = blockIdx.z;
    int m0 = blockIdx.y * 128;
    int n0 = blockIdx.x * 128;
    int tid = threadIdx.x;
    int wid = tid >> 5, lane = tid & 31;
    int warp_m = wid & 1;      // 2 warps over M
    int warp_n = wid >> 1;     // 4 warps over N

    const __nv_bfloat16* Ab = (const __nv_bfloat16*)((aSel >= 0) ? buf(aSel) : aExt)
                              + aOff + (long)b * aStride;
    const __nv_bfloat16* Bb = (const __nv_bfloat16*)((bSel >= 0) ? buf(bSel) : bExt)
                              + bOff + (long)b * bStride;

    uint32_t sA_a = smem_u32(sA);
    uint32_t sB_a = smem_u32(sB);

    // global->smem staging: 512 x 16B per operand per stage
    int ldr = tid >> 2, ldseg = tid & 3;
    uint32_t dstOffLo = swz_addr(ldr, ldseg);
    uint32_t dstOffHi = swz_addr(ldr + 64, ldseg);

    // ldmatrix base-relative addresses for kki=0 (kki=1 is ^0x20)
    int lr = lane & 15, lk = lane >> 4;
    uint32_t ar0 = swz_addr(warp_m * 64 + lr, lk);
    uint32_t ar1 = swz_addr(warp_m * 64 + 16 + lr, lk);
    uint32_t ar2 = swz_addr(warp_m * 64 + 32 + lr, lk);
    uint32_t ar3 = swz_addr(warp_m * 64 + 48 + lr, lk);
    uint32_t br0 = swz_addr(warp_n * 32 + lr, lk);
    uint32_t br1 = swz_addr(warp_n * 32 + 16 + lr, lk);

    F4 c00 = {0,0,0,0}, c01 = {0,0,0,0}, c02 = {0,0,0,0}, c03 = {0,0,0,0};
    F4 c10 = {0,0,0,0}, c11 = {0,0,0,0}, c12 = {0,0,0,0}, c13 = {0,0,0,0};
    F4 c20 = {0,0,0,0}, c21 = {0,0,0,0}, c22 = {0,0,0,0}, c23 = {0,0,0,0};
    F4 c30 = {0,0,0,0}, c31 = {0,0,0,0}, c32 = {0,0,0,0}, c33 = {0,0,0,0};

    int nStages = K >> 5;

    // prefetch stage 0
    {
        const __nv_bfloat16* as = Ab + (long)(m0 + ldr) * ldA + ldseg * 8;
        const __nv_bfloat16* bs = Bb + (long)(n0 + ldr) * ldB + ldseg * 8;
        CP16(sA_a + dstOffLo, as);
        CP16(sB_a + dstOffLo, bs);
        CP16(sA_a + dstOffHi, as + (long)64 * ldA);
        CP16(sB_a + dstOffHi, bs + (long)64 * ldB);
        CP_COMMIT();
    }

    for (int ks = 0; ks < nStages; ks++) {
        if (ks + 1 < nStages) {
            int k0 = (ks + 1) << 5;
            uint32_t stoff = (uint32_t)(((ks + 1) & 1) * 8192);
            const __nv_bfloat16* as = Ab + (long)(m0 + ldr) * ldA + k0 + ldseg * 8;
            const __nv_bfloat16* bs = Bb + (long)(n0 + ldr) * ldB + k0 + ldseg * 8;
            CP16(sA_a + stoff + dstOffLo, as);
            CP16(sB_a + stoff + dstOffLo, bs);
            CP16(sA_a + stoff + dstOffHi, as + (long)64 * ldA);
            CP16(sB_a + stoff + dstOffHi, bs + (long)64 * ldB);
            CP_COMMIT();
            CP_WAIT(1);
        } else {
            CP_WAIT(0);
        }
        __syncthreads();

        uint32_t stoff = (uint32_t)((ks & 1) * 8192);
        uint32_t aBase = sA_a + stoff;
        uint32_t bBase = sB_a + stoff;
        LOAD_MMA(0u);
        LOAD_MMA(0x20u);
        __syncthreads();
    }

    // ---------------- epilogue (named structs, scalar only) ------------------
    int rowBase = m0 + warp_m * 64 + (lane >> 2);
    int colBase = n0 + warp_n * 32 + (lane & 3) * 2;

#define EPI_TILE(CT, MT, NT) do { \
    int r0 = rowBase + (MT) * 16; \
    int cc = colBase + (NT) * 8; \
    float d0 = CT.a, d1 = CT.b, d2 = CT.c, d3 = CT.d; \
    if (EPI == 0 || EPI == 2) { \
        float b0 = 0.f, b1 = 0.f; \
        if (EPI == 0) { b0 = bias[cc]; b1 = bias[cc + 1]; } \
        __nv_bfloat16* Cb = (__nv_bfloat16*)((cSel >= 0) ? buf(cSel) : cExt) \
                            + (long)b * cStride; \
        __nv_bfloat162 v0 = __floats2bfloat162_rn(d0 + b0, d1 + b1); \
        __nv_bfloat162 v1 = __floats2bfloat162_rn(d2 + b0, d3 + b1); \
        *(uint32_t*)(Cb + (long)r0 * ldC + cc) = *(uint32_t*)&v0; \
        *(uint32_t*)(Cb + (long)(r0 + 8) * ldC + cc) = *(uint32_t*)&v1; \
    } else if (EPI == 1) { \
        float* Cf = (float*)((cSel >= 0) ? buf(cSel) : cExt) + (long)b * cStride; \
        float2 v0 = make_float2(d0 * alpha, d1 * alpha); \
        float2 v1 = make_float2(d2 * alpha, d3 * alpha); \
        *(float2*)(Cf + (long)r0 * ldC + cc) = v0; \
        *(float2*)(Cf + (long)(r0 + 8) * ldC + cc) = v1; \
    } else { \
        float* Cf = (float*)((cSel >= 0) ? buf(cSel) : cExt) + (long)b * cStride; \
        float bi0 = bias[r0], bi8 = bias[r0 + 8]; \
        float gv0 = g_gate[b * CC + r0], gv8 = g_gate[b * CC + r0 + 8]; \
        float2 rv0 = *(const float2*)(resid + (long)b * strideR + (long)r0 * ldC + cc); \
        float2 rv8 = *(const float2*)(resid + (long)b * strideR + (long)(r0 + 8) * ldC + cc); \
        float2 v0 = make_float2(rv0.x + gv0 * (d0 + bi0), rv0.y + gv0 * (d1 + bi0)); \
        float2 v1 = make_float2(rv8.x + gv8 * (d2 + bi8), rv8.y + gv8 * (d3 + bi8)); \
        *(float2*)(Cf + (long)r0 * ldC + cc) = v0; \
        *(float2*)(Cf + (long)(r0 + 8) * ldC + cc) = v1; \
    } \
} while (0)

    EPI_TILE(c00, 0, 0); EPI_TILE(c01, 0, 1); EPI_TILE(c02, 0, 2); EPI_TILE(c03, 0, 3);
    EPI_TILE(c10, 1, 0); EPI_TILE(c11, 1, 1); EPI_TILE(c12, 1, 2); EPI_TILE(c13, 1, 3);
    EPI_TILE(c20, 2, 0); EPI_TILE(c21, 2, 1); EPI_TILE(c22, 2, 2); EPI_TILE(c23, 2, 3);
    EPI_TILE(c30, 3, 0); EPI_TILE(c31, 3, 1); EPI_TILE(c32, 3, 2); EPI_TILE(c33, 3, 3);
#undef EPI_TILE
}

// ------------------------- launch --------------------------------------------
extern "C" void kernel_launch(void* const* d_in, const int* in_sizes, int n_in,
                              void* d_out, int out_size) {
    const float* x        = (const float*)d_in[0];
    const float* gn_gamma = (const float*)d_in[1];
    const float* gn_beta  = (const float*)d_in[2];
    const float* w_qkv    = (const float*)d_in[3];
    const float* b_qkv    = (const float*)d_in[4];
    const float* w_proj   = (const float*)d_in[5];
    const float* b_proj   = (const float*)d_in[6];
    const float* w_se1    = (const float*)d_in[7];
    const float* b_se1    = (const float*)d_in[8];
    const float* w_se2    = (const float*)d_in[9];
    const float* b_se2    = (const float*)d_in[10];
    float* out = (float*)d_out;

    // weight conversions to bf16
    convw_k<<<(O3 * CC + 255) / 256, 256>>>(w_qkv, 6, O3 * CC);
    convw_k<<<(CC * CC + 255) / 256, 256>>>(w_proj, 7, CC * CC);

    // GN stats + pooled means (one pass over x)
    gn_stats_k<<<dim3(NGROUP, BB), 256>>>(x, gn_gamma, gn_beta);

    // SE gate
    se_k<<<BB, 256>>>(w_se1, b_se1, w_se2, b_se2);

    // xnT = GN(x)^T bf16 [b, n, c]
    xnT_k<<<dim3(NN / 32, CC / 32, BB), dim3(32, 8)>>>(x);

    // QKV: D[n, o] = xnT[n,:] . W[o,:]  + bias[o]  -> qkvT bf16
    gemm_mma<0><<<dim3(O3 / 128, NN / 128, BB), 256>>>(
        0, nullptr, 0L, (long)NN * CC, CC,
        6, nullptr, 0L, 0L, CC,
        1, nullptr, (long)NN * O3, O3,
        CC, 1.0f, b_qkv, nullptr, 0L);

    // scores: D[i, j] = q_i . k_j * 1/16 -> g_attn fp32
    gemm_mma<1><<<dim3(NN / 128, NN / 128, BB), 256>>>(
        1, nullptr, 0L, (long)NN * O3, O3,
        1, nullptr, 256L, (long)NN * O3, O3,
        2, nullptr, (long)NN * NN, NN,
        CC, 0.0625f, nullptr, nullptr, 0L);

    // softmax rows -> bf16
    softmax_k<<<BB * NN, 256>>>();

    // vK = v^T (K-major over j)
    vT_k<<<dim3(NN / 32, CC / 32, BB), dim3(32, 8)>>>();

    // x_attn: D[i, c] = attn[i,:] . vK[c,:] -> xattnT bf16
    gemm_mma<2><<<dim3(CC / 128, NN / 128, BB), 256>>>(
        3, nullptr, 0L, (long)NN * NN, NN,
        4, nullptr, 0L, (long)CC * NN, NN,
        5, nullptr, (long)NN * CC, CC,
        NN, 1.0f, nullptr, nullptr, 0L);

    // proj: D[c, n] = Wp[c,:] . xattnT[n,:]; out = x + gate*(D + bias)
    gemm_mma<3><<<dim3(NN / 128, CC / 128, BB), 256>>>(
        7, nullptr, 0L, 0L, CC,
        5, nullptr, 0L, (long)NN * CC, CC,
        -1, out, (long)CC * NN, NN,
        CC, 1.0f, b_proj, x, (long)CC * NN);
}

// round 10
// speedup vs baseline: 4.1975x; 1.0436x over previous
#include <cuda_runtime.h>
#include <cuda_bf16.h>
#include <math.h>
#include <stdint.h>

#define BB 32
#define CC 256
#define NN 1024
#define O3 768
#define NGROUP 32
#define GN_EPS 1e-5f

// ------------------------- scratch (device globals; no allocs) ---------------
__device__ __nv_bfloat16 g_xnT[BB * NN * CC];         // 16.8 MB  [b, n, c]
__device__ __nv_bfloat16 g_qkvT[BB * NN * O3];        // 50.3 MB  [b, n, o]
__device__ __nv_bfloat16 g_attnb[(long)BB * NN * NN]; // 67 MB    [b, i, j] bf16 scores->softmax in place
__device__ __nv_bfloat16 g_vK[BB * CC * NN];          // 16.8 MB  [b, c, j]
__device__ __nv_bfloat16 g_xattnT[BB * NN * CC];      // 16.8 MB  [b, i, c]
__device__ __nv_bfloat16 g_wqkv_b[O3 * CC];
__device__ __nv_bfloat16 g_wproj_b[CC * CC];
__device__ float g_pooled[BB * CC];
__device__ float g_gate[BB * CC];
__device__ float g_gnsc[BB * CC];
__device__ float g_gnof[BB * CC];

__device__ __forceinline__ void* buf(int s) {
    switch (s) {
        case 0: return (void*)g_xnT;
        case 1: return (void*)g_qkvT;
        case 3: return (void*)g_attnb;
        case 4: return (void*)g_vK;
        case 5: return (void*)g_xattnT;
        case 6: return (void*)g_wqkv_b;
        case 7: return (void*)g_wproj_b;
        default: return nullptr;
    }
}

// ------------------------- PTX macros ----------------------------------------
__device__ __forceinline__ uint32_t smem_u32(const void* p) {
    return (uint32_t)__cvta_generic_to_shared(p);
}
#define CP16(dst, src) \
    asm volatile("cp.async.cg.shared.global [%0], [%1], 16;" :: "r"(dst), "l"(src))
#define CP_COMMIT() asm volatile("cp.async.commit_group;")
#define CP_WAIT(N)  asm volatile("cp.async.wait_group %0;" :: "n"(N))

#define LDM4(f0, f1, f2, f3, addr) \
    asm volatile("ldmatrix.sync.aligned.m8n8.x4.shared.b16 {%0,%1,%2,%3}, [%4];" \
                 : "=r"(f0), "=r"(f1), "=r"(f2), "=r"(f3) : "r"(addr))

#define MMA16(d0, d1, d2, d3, a0, a1, a2, a3, b0, b1) \
    asm volatile( \
        "mma.sync.aligned.m16n8k16.row.col.f32.bf16.bf16.f32 " \
        "{%0,%1,%2,%3}, {%4,%5,%6,%7}, {%8,%9}, {%0,%1,%2,%3};" \
        : "+f"(d0), "+f"(d1), "+f"(d2), "+f"(d3) \
        : "r"(a0), "r"(a1), "r"(a2), "r"(a3), "r"(b0), "r"(b1))

struct U4 { uint32_t a, b, c, d; };
struct F4 { float a, b, c, d; };

__device__ __forceinline__ uint32_t swz_addr(int r, int seg) {
    return (uint32_t)(r * 64 + ((seg ^ ((r >> 1) & 3)) << 4));
}

__device__ __forceinline__ float warpSum(float v) {
    #pragma unroll
    for (int o = 16; o; o >>= 1) v += __shfl_xor_sync(0xFFFFFFFFu, v, o);
    return v;
}
__device__ __forceinline__ float warpMax(float v) {
    #pragma unroll
    for (int o = 16; o; o >>= 1) v = fmaxf(v, __shfl_xor_sync(0xFFFFFFFFu, v, o));
    return v;
}

// ------------------------- fp32 -> bf16 weight convert -----------------------
__global__ void convw_k(const float* __restrict__ in, int outSel, int n) {
    __nv_bfloat16* out = (__nv_bfloat16*)buf(outSel);
    int i = blockIdx.x * 256 + threadIdx.x;
    if (i < n) out[i] = __float2bfloat16(in[i]);
}

// ------------------------- GN stats + pooled mean ----------------------------
__global__ void gn_stats_k(const float* __restrict__ x,
                           const float* __restrict__ gamma,
                           const float* __restrict__ beta) {
    int g = blockIdx.x, b = blockIdx.y;
    long base = ((long)b * CC + g * 8) * NN;
    const float* p = x + base;
    int t = threadIdx.x;
    int lane = t & 31, w = t >> 5;

    float cs[8];
    float ss = 0.f;
    #pragma unroll
    for (int it = 0; it < 8; it++) {
        float4 v = *(const float4*)&p[t * 4 + it * 1024];
        cs[it] = v.x + v.y + v.z + v.w;
        ss += v.x * v.x + v.y * v.y + v.z * v.z + v.w * v.w;
    }
    #pragma unroll
    for (int it = 0; it < 8; it++) cs[it] = warpSum(cs[it]);
    ss = warpSum(ss);

    __shared__ float rcs[8][8];
    __shared__ float rss[8];
    __shared__ float smean, srstd;
    __shared__ float chsum[8];
    if (lane == 0) {
        #pragma unroll
        for (int it = 0; it < 8; it++) rcs[w][it] = cs[it];
        rss[w] = ss;
    }
    __syncthreads();
    if (t < 8) {
        float a = 0.f;
        #pragma unroll
        for (int i = 0; i < 8; i++) a += rcs[i][t];
        chsum[t] = a;
        g_pooled[b * CC + g * 8 + t] = a * (1.0f / 1024.0f);
    }
    __syncthreads();
    if (t == 0) {
        float a = 0.f, c2 = 0.f;
        #pragma unroll
        for (int i = 0; i < 8; i++) { a += chsum[i]; c2 += rss[i]; }
        float mean = a * (1.0f / 8192.0f);
        float var = c2 * (1.0f / 8192.0f) - mean * mean;
        smean = mean;
        srstd = rsqrtf(var + GN_EPS);
    }
    __syncthreads();
    if (t < 8) {
        int c = g * 8 + t;
        float sc = gamma[c] * srstd;
        g_gnsc[b * CC + c] = sc;
        g_gnof[b * CC + c] = beta[c] - smean * sc;
    }
}

// ------------------------- SE gate (parallelized) ----------------------------
// block = batch; layer1: output o computed by 4 threads (t = o*4+q), each
// summing 64 elems, quad shfl-reduce; layer2: one output per thread from smem.
__global__ void se_k(const float* __restrict__ w1, const float* __restrict__ b1,
                     const float* __restrict__ w2, const float* __restrict__ b2) {
    int b = blockIdx.x;
    int t = threadIdx.x;
    __shared__ float pool[CC];
    __shared__ float h1[64];
    pool[t] = g_pooled[b * CC + t];
    __syncthreads();
    {
        int o = t >> 2, q = t & 3;
        const float* wr = w1 + o * CC + q * 64;
        const float* pp = pool + q * 64;
        float s = 0.f;
        #pragma unroll 16
        for (int i = 0; i < 64; i++) s += wr[i] * pp[i];
        s += __shfl_down_sync(0xFFFFFFFFu, s, 2);
        s += __shfl_down_sync(0xFFFFFFFFu, s, 1);
        if (q == 0) h1[o] = fmaxf(s + b1[o], 0.0f);
    }
    __syncthreads();
    float s = b2[t];
    const float* wr = w2 + t * 64;
    #pragma unroll
    for (int j = 0; j < 64; j++) s += wr[j] * h1[j];
    g_gate[b * CC + t] = 1.0f / (1.0f + expf(-s));
}

// ------------------------- xnT: GN(x) transposed to [b,n,c] bf16 -------------
__global__ void xnT_k(const float* __restrict__ x) {
    __shared__ float tile[32][33];
    int b = blockIdx.z;
    int cblk = blockIdx.y * 32, nblk = blockIdx.x * 32;
    int tx = threadIdx.x, ty = threadIdx.y;   // (32, 8)
    #pragma unroll
    for (int i = 0; i < 4; i++) {
        int c = cblk + ty + i * 8;
        float sc = g_gnsc[b * CC + c];
        float of = g_gnof[b * CC + c];
        tile[ty + i * 8][tx] = x[((long)b * CC + c) * NN + nblk + tx] * sc + of;
    }
    __syncthreads();
    #pragma unroll
    for (int i = 0; i < 4; i++) {
        int n = nblk + ty + i * 8;
        g_xnT[((long)b * NN + n) * CC + cblk + tx] = __float2bfloat16(tile[tx][ty + i * 8]);
    }
}

// ------------------------- vT: qkvT[:,512:768] -> vK [b,c,j] -----------------
__global__ void vT_k() {
    __shared__ __nv_bfloat16 tile[32][33];
    int b = blockIdx.z;
    int cblk = blockIdx.y * 32, jblk = blockIdx.x * 32;
    int tx = threadIdx.x, ty = threadIdx.y;   // (32, 8)
    #pragma unroll
    for (int i = 0; i < 4; i++) {
        int j = jblk + ty + i * 8;
        tile[ty + i * 8][tx] = g_qkvT[((long)b * NN + j) * O3 + 512 + cblk + tx];
    }
    __syncthreads();
    #pragma unroll
    for (int i = 0; i < 4; i++) {
        int c = cblk + ty + i * 8;
        g_vK[((long)b * CC + c) * NN + jblk + tx] = tile[tx][ty + i * 8];
    }
}

// ------------------------- softmax rows: bf16 in/out, fp32 internal ----------
__global__ void softmax_k() {
    long row = blockIdx.x;
    __nv_bfloat16* q = g_attnb + row * NN;
    int t = threadIdx.x;
    uint2 pk = *(uint2*)&q[t * 4];
    __nv_bfloat162 lo = *(__nv_bfloat162*)&pk.x;
    __nv_bfloat162 hi = *(__nv_bfloat162*)&pk.y;
    float4 v;
    v.x = __bfloat162float(lo.x); v.y = __bfloat162float(lo.y);
    v.z = __bfloat162float(hi.x); v.w = __bfloat162float(hi.y);
    float m = fmaxf(fmaxf(v.x, v.y), fmaxf(v.z, v.w));
    m = warpMax(m);
    __shared__ float rs[8];
    __shared__ float bc;
    int lane = t & 31, w = t >> 5;
    if (lane == 0) rs[w] = m;
    __syncthreads();
    if (t == 0) {
        float mm = rs[0];
        #pragma unroll
        for (int i = 1; i < 8; i++) mm = fmaxf(mm, rs[i]);
        bc = mm;
    }
    __syncthreads();
    m = bc;
    v.x = expf(v.x - m); v.y = expf(v.y - m);
    v.z = expf(v.z - m); v.w = expf(v.w - m);
    float s = v.x + v.y + v.z + v.w;
    s = warpSum(s);
    if (lane == 0) rs[w] = s;
    __syncthreads();
    if (t == 0) {
        float ss = 0.f;
        #pragma unroll
        for (int i = 0; i < 8; i++) ss += rs[i];
        bc = 1.0f / ss;
    }
    __syncthreads();
    float inv = bc;
    __nv_bfloat162 olo = __floats2bfloat162_rn(v.x * inv, v.y * inv);
    __nv_bfloat162 ohi = __floats2bfloat162_rn(v.z * inv, v.w * inv);
    uint2 opk;
    opk.x = *(uint32_t*)&olo;
    opk.y = *(uint32_t*)&ohi;
    *(uint2*)&q[t * 4] = opk;
}

// ------------------------- HMMA GEMM: D[M,N] = A[M,K] @ B[N,K]^T -------------
// EPI 0: bf16 out = acc + bias[col]  |  EPI 1: bf16 out = acc*alpha
// EPI 2: bf16 out = acc              |  EPI 3: fp32 out = resid + g_gate*(acc+bias[row])

#define MMA_ALL() do { \
    MMA16(c00.a,c00.b,c00.c,c00.d, af0.a,af0.b,af0.c,af0.d, bf0.a,bf0.c); \
    MMA16(c01.a,c01.b,c01.c,c01.d, af0.a,af0.b,af0.c,af0.d, bf0.b,bf0.d); \
    MMA16(c02.a,c02.b,c02.c,c02.d, af0.a,af0.b,af0.c,af0.d, bf1.a,bf1.c); \
    MMA16(c03.a,c03.b,c03.c,c03.d, af0.a,af0.b,af0.c,af0.d, bf1.b,bf1.d); \
    MMA16(c10.a,c10.b,c10.c,c10.d, af1.a,af1.b,af1.c,af1.d, bf0.a,bf0.c); \
    MMA16(c11.a,c11.b,c11.c,c11.d, af1.a,af1.b,af1.c,af1.d, bf0.b,bf0.d); \
    MMA16(c12.a,c12.b,c12.c,c12.d, af1.a,af1.b,af1.c,af1.d, bf1.a,bf1.c); \
    MMA16(c13.a,c13.b,c13.c,c13.d, af1.a,af1.b,af1.c,af1.d, bf1.b,bf1.d); \
    MMA16(c20.a,c20.b,c20.c,c20.d, af2.a,af2.b,af2.c,af2.d, bf0.a,bf0.c); \
    MMA16(c21.a,c21.b,c21.c,c21.d, af2.a,af2.b,af2.c,af2.d, bf0.b,bf0.d); \
    MMA16(c22.a,c22.b,c22.c,c22.d, af2.a,af2.b,af2.c,af2.d, bf1.a,bf1.c); \
    MMA16(c23.a,c23.b,c23.c,c23.d, af2.a,af2.b,af2.c,af2.d, bf1.b,bf1.d); \
    MMA16(c30.a,c30.b,c30.c,c30.d, af3.a,af3.b,af3.c,af3.d, bf0.a,bf0.c); \
    MMA16(c31.a,c31.b,c31.c,c31.d, af3.a,af3.b,af3.c,af3.d, bf0.b,bf0.d); \
    MMA16(c32.a,c32.b,c32.c,c32.d, af3.a,af3.b,af3.c,af3.d, bf1.a,bf1.c); \
    MMA16(c33.a,c33.b,c33.c,c33.d, af3.a,af3.b,af3.c,af3.d, bf1.b,bf1.d); \
} while (0)

#define LOAD_MMA(KOFF) do { \
    U4 af0, af1, af2, af3, bf0, bf1; \
    LDM4(af0.a,af0.b,af0.c,af0.d, aBase + (ar0 ^ (KOFF))); \
    LDM4(af1.a,af1.b,af1.c,af1.d, aBase + (ar1 ^ (KOFF))); \
    LDM4(af2.a,af2.b,af2.c,af2.d, aBase + (ar2 ^ (KOFF))); \
    LDM4(af3.a,af3.b,af3.c,af3.d, aBase + (ar3 ^ (KOFF))); \
    LDM4(bf0.a,bf0.b,bf0.c,bf0.d, bBase + (br0 ^ (KOFF))); \
    LDM4(bf1.a,bf1.b,bf1.c,bf1.d, bBase + (br1 ^ (KOFF))); \
    MMA_ALL(); \
} while (0)

template <int EPI>
__global__ __launch_bounds__(256) void gemm_mma(
    int aSel, const void* aExt, long aOff, long aStride, int ldA,
    int bSel, const void* bExt, long bOff, long bStride, int ldB,
    int cSel, void* cExt, long cStride, int ldC,
    int K, float alpha,
    const float* __restrict__ bias,
    const float* __restrict__ resid, long strideR) {
    __shared__ alignas(1024) uint8_t sA[2][128 * 64];
    __shared__ alignas(1024) uint8_t sB[2][128 * 64];

    int b = blockIdx.z;
    int m0 = blockIdx.y * 128;
    int n0 = blockIdx.x * 128;
    int tid = threadIdx.x;
    int wid = tid >> 5, lane = tid & 31;
    int warp_m = wid & 1;
    int warp_n = wid >> 1;

    const __nv_bfloat16* Ab = (const __nv_bfloat16*)((aSel >= 0) ? buf(aSel) : aExt)
                              + aOff + (long)b * aStride;
    const __nv_bfloat16* Bb = (const __nv_bfloat16*)((bSel >= 0) ? buf(bSel) : bExt)
                              + bOff + (long)b * bStride;

    uint32_t sA_a = smem_u32(sA);
    uint32_t sB_a = smem_u32(sB);

    int ldr = tid >> 2, ldseg = tid & 3;
    uint32_t dstOffLo = swz_addr(ldr, ldseg);
    uint32_t dstOffHi = swz_addr(ldr + 64, ldseg);

    int lr = lane & 15, lk = lane >> 4;
    uint32_t ar0 = swz_addr(warp_m * 64 + lr, lk);
    uint32_t ar1 = swz_addr(warp_m * 64 + 16 + lr, lk);
    uint32_t ar2 = swz_addr(warp_m * 64 + 32 + lr, lk);
    uint32_t ar3 = swz_addr(warp_m * 64 + 48 + lr, lk);
    uint32_t br0 = swz_addr(warp_n * 32 + lr, lk);
    uint32_t br1 = swz_addr(warp_n * 32 + 16 + lr, lk);

    F4 c00 = {0,0,0,0}, c01 = {0,0,0,0}, c02 = {0,0,0,0}, c03 = {0,0,0,0};
    F4 c10 = {0,0,0,0}, c11 = {0,0,0,0}, c12 = {0,0,0,0}, c13 = {0,0,0,0};
    F4 c20 = {0,0,0,0}, c21 = {0,0,0,0}, c22 = {0,0,0,0}, c23 = {0,0,0,0};
    F4 c30 = {0,0,0,0}, c31 = {0,0,0,0}, c32 = {0,0,0,0}, c33 = {0,0,0,0};

    int nStages = K >> 5;

    {
        const __nv_bfloat16* as = Ab + (long)(m0 + ldr) * ldA + ldseg * 8;
        const __nv_bfloat16* bs = Bb + (long)(n0 + ldr) * ldB + ldseg * 8;
        CP16(sA_a + dstOffLo, as);
        CP16(sB_a + dstOffLo, bs);
        CP16(sA_a + dstOffHi, as + (long)64 * ldA);
        CP16(sB_a + dstOffHi, bs + (long)64 * ldB);
        CP_COMMIT();
    }

    for (int ks = 0; ks < nStages; ks++) {
        if (ks + 1 < nStages) {
            int k0 = (ks + 1) << 5;
            uint32_t stoff = (uint32_t)(((ks + 1) & 1) * 8192);
            const __nv_bfloat16* as = Ab + (long)(m0 + ldr) * ldA + k0 + ldseg * 8;
            const __nv_bfloat16* bs = Bb + (long)(n0 + ldr) * ldB + k0 + ldseg * 8;
            CP16(sA_a + stoff + dstOffLo, as);
            CP16(sB_a + stoff + dstOffLo, bs);
            CP16(sA_a + stoff + dstOffHi, as + (long)64 * ldA);
            CP16(sB_a + stoff + dstOffHi, bs + (long)64 * ldB);
            CP_COMMIT();
            CP_WAIT(1);
        } else {
            CP_WAIT(0);
        }
        __syncthreads();

        uint32_t stoff = (uint32_t)((ks & 1) * 8192);
        uint32_t aBase = sA_a + stoff;
        uint32_t bBase = sB_a + stoff;
        LOAD_MMA(0u);
        LOAD_MMA(0x20u);
        __syncthreads();
    }

    int rowBase = m0 + warp_m * 64 + (lane >> 2);
    int colBase = n0 + warp_n * 32 + (lane & 3) * 2;

#define EPI_TILE(CT, MT, NT) do { \
    int r0 = rowBase + (MT) * 16; \
    int cc = colBase + (NT) * 8; \
    float d0 = CT.a, d1 = CT.b, d2 = CT.c, d3 = CT.d; \
    if (EPI == 0 || EPI == 1 || EPI == 2) { \
        float b0 = 0.f, b1 = 0.f; \
        if (EPI == 0) { b0 = bias[cc]; b1 = bias[cc + 1]; } \
        if (EPI == 1) { d0 *= alpha; d1 *= alpha; d2 *= alpha; d3 *= alpha; } \
        __nv_bfloat16* Cb = (__nv_bfloat16*)((cSel >= 0) ? buf(cSel) : cExt) \
                            + (long)b * cStride; \
        __nv_bfloat162 v0 = __floats2bfloat162_rn(d0 + b0, d1 + b1); \
        __nv_bfloat162 v1 = __floats2bfloat162_rn(d2 + b0, d3 + b1); \
        *(uint32_t*)(Cb + (long)r0 * ldC + cc) = *(uint32_t*)&v0; \
        *(uint32_t*)(Cb + (long)(r0 + 8) * ldC + cc) = *(uint32_t*)&v1; \
    } else { \
        float* Cf = (float*)((cSel >= 0) ? buf(cSel) : cExt) + (long)b * cStride; \
        float bi0 = bias[r0], bi8 = bias[r0 + 8]; \
        float gv0 = g_gate[b * CC + r0], gv8 = g_gate[b * CC + r0 + 8]; \
        float2 rv0 = *(const float2*)(resid + (long)b * strideR + (long)r0 * ldC + cc); \
        float2 rv8 = *(const float2*)(resid + (long)b * strideR + (long)(r0 + 8) * ldC + cc); \
        float2 v0 = make_float2(rv0.x + gv0 * (d0 + bi0), rv0.y + gv0 * (d1 + bi0)); \
        float2 v1 = make_float2(rv8.x + gv8 * (d2 + bi8), rv8.y + gv8 * (d3 + bi8)); \
        *(float2*)(Cf + (long)r0 * ldC + cc) = v0; \
        *(float2*)(Cf + (long)(r0 + 8) * ldC + cc) = v1; \
    } \
} while (0)

    EPI_TILE(c00, 0, 0); EPI_TILE(c01, 0, 1); EPI_TILE(c02, 0, 2); EPI_TILE(c03, 0, 3);
    EPI_TILE(c10, 1, 0); EPI_TILE(c11, 1, 1); EPI_TILE(c12, 1, 2); EPI_TILE(c13, 1, 3);
    EPI_TILE(c20, 2, 0); EPI_TILE(c21, 2, 1); EPI_TILE(c22, 2, 2); EPI_TILE(c23, 2, 3);
    EPI_TILE(c30, 3, 0); EPI_TILE(c31, 3, 1); EPI_TILE(c32, 3, 2); EPI_TILE(c33, 3, 3);
#undef EPI_TILE
}

// ------------------------- launch --------------------------------------------
extern "C" void kernel_launch(void* const* d_in, const int* in_sizes, int n_in,
                              void* d_out, int out_size) {
    const float* x        = (const float*)d_in[0];
    const float* gn_gamma = (const float*)d_in[1];
    const float* gn_beta  = (const float*)d_in[2];
    const float* w_qkv    = (const float*)d_in[3];
    const float* b_qkv    = (const float*)d_in[4];
    const float* w_proj   = (const float*)d_in[5];
    const float* b_proj   = (const float*)d_in[6];
    const float* w_se1    = (const float*)d_in[7];
    const float* b_se1    = (const float*)d_in[8];
    const float* w_se2    = (const float*)d_in[9];
    const float* b_se2    = (const float*)d_in[10];
    float* out = (float*)d_out;

    convw_k<<<(O3 * CC + 255) / 256, 256>>>(w_qkv, 6, O3 * CC);
    convw_k<<<(CC * CC + 255) / 256, 256>>>(w_proj, 7, CC * CC);

    gn_stats_k<<<dim3(NGROUP, BB), 256>>>(x, gn_gamma, gn_beta);
    se_k<<<BB, 256>>>(w_se1, b_se1, w_se2, b_se2);

    xnT_k<<<dim3(NN / 32, CC / 32, BB), dim3(32, 8)>>>(x);

    // QKV: D[n, o] = xnT[n,:] . W[o,:]  + bias[o]  -> qkvT bf16
    gemm_mma<0><<<dim3(O3 / 128, NN / 128, BB), 256>>>(
        0, nullptr, 0L, (long)NN * CC, CC,
        6, nullptr, 0L, 0L, CC,
        1, nullptr, (long)NN * O3, O3,
        CC, 1.0f, b_qkv, nullptr, 0L);

    // scores: D[i, j] = q_i . k_j * 1/16 -> g_attnb bf16 (in-place softmax next)
    gemm_mma<1><<<dim3(NN / 128, NN / 128, BB), 256>>>(
        1, nullptr, 0L, (long)NN * O3, O3,
        1, nullptr, 256L, (long)NN * O3, O3,
        3, nullptr, (long)NN * NN, NN,
        CC, 0.0625f, nullptr, nullptr, 0L);

    // softmax rows bf16 in-place
    softmax_k<<<BB * NN, 256>>>();

    // vK = v^T (K-major over j)
    vT_k<<<dim3(NN / 32, CC / 32, BB), dim3(32, 8)>>>();

    // x_attn: D[i, c] = attn[i,:] . vK[c,:] -> xattnT bf16
    gemm_mma<2><<<dim3(CC / 128, NN / 128, BB), 256>>>(
        3, nullptr, 0L, (long)NN * NN, NN,
        4, nullptr, 0L, (long)CC * NN, NN,
        5, nullptr, (long)NN * CC, CC,
        NN, 1.0f, nullptr, nullptr, 0L);

    // proj: D[c, n] = Wp[c,:] . xattnT[n,:]; out = x + gate*(D + bias)
    gemm_mma<3><<<dim3(NN / 128, CC / 128, BB), 256>>>(
        7, nullptr, 0L, 0L, CC,
        5, nullptr, 0L, (long)NN * CC, CC,
        -1, out, (long)CC * NN, NN,
        CC, 1.0f, b_proj, x, (long)CC * NN);
}